// round 9
// baseline (speedup 1.0000x reference)
#include <cuda_runtime.h>
#include <cstdint>

// Problem constants (fixed by the dataset)
#define BB 32
#define TT 2048
#define KK 512
#define MM 1024          // MAX_MASKED
#define MU 1024          // MAX_UNMASKED
#define K4 (KK / 4)      // 128 float4 per row
#define ROWS 4           // rows per block
#define LN_EPS 1e-5f

// Round-6 structure (empirical best) with ONE change: default .wb stores
// instead of __stcs streaming stores (A/B test of store cache policy).
// Block = 128 threads, ROWS consecutive rows of one batch.
// Single __syncthreads per block; all gather loads front-batched (MLP=8).
// Outputs (concatenated in d_out):
//   out0: unmasked_embeddings (B, MU, K)
//   out1: mask_embedding      (B, MM, K)
//   out2: unmasked_positions  (B, MU, K)
__global__ __launch_bounds__(128, 8)
void mae_masking_kernel(
    const float* __restrict__ tok,    // (B, T, K)
    const float* __restrict__ pe,     // (T, K)
    const float* __restrict__ mw,     // (K, 1)
    const float* __restrict__ gamma,  // (K,)
    const float* __restrict__ beta,   // (K,)
    const int*   __restrict__ midx,   // (B, MM)
    const int*   __restrict__ uidx,   // (B, MU)
    const int*   __restrict__ nm,     // (B,)
    const int*   __restrict__ nu,     // (B,)
    float* __restrict__ out)
{
    const int j0 = blockIdx.x * ROWS;
    const int b  = blockIdx.y;
    const int t  = threadIdx.x;        // 0..127, float4 lane
    const int wid = t >> 5, lane = t & 31;

    const int nmb = nm[b];
    const int nub = nu[b];
    const bool anyM = j0 < nmb;        // block-uniform
    const bool anyU = j0 < nub;        // block-uniform

    const float4* __restrict__ pe4  = reinterpret_cast<const float4*>(pe);
    const float4* __restrict__ tok4 = reinterpret_cast<const float4*>(tok);
    float4* __restrict__ o0 = reinterpret_cast<float4*>(out);
    float4* __restrict__ o1 = o0 + (size_t)BB * MU * K4;
    float4* __restrict__ o2 = o1 + (size_t)BB * MM * K4;

    const float4 zero = make_float4(0.f, 0.f, 0.f, 0.f);
    const size_t rowbase = ((size_t)b * MU + (size_t)j0) * K4 + (size_t)t;

    __shared__ float4 sg[K4], sbe[K4];
    __shared__ float  sh_s[ROWS][4], sh_ss[ROWS][4];

    // ---------------- Pass A: pass-through copies, no syncs ----------------
    {
        float4 tk[ROWS], peu[ROWS];
        if (anyU) {
            int u[ROWS];
            #pragma unroll
            for (int r = 0; r < ROWS; r++) u[r] = uidx[b * MU + j0 + r];
            #pragma unroll
            for (int r = 0; r < ROWS; r++) {           // 8 independent loads
                if (j0 + r < nub) {
                    peu[r] = pe4[(size_t)u[r] * K4 + t];
                    tk[r]  = tok4[((size_t)b * TT + (size_t)u[r]) * K4 + t];
                } else { peu[r] = zero; tk[r] = zero; }
            }
        } else {
            #pragma unroll
            for (int r = 0; r < ROWS; r++) { peu[r] = zero; tk[r] = zero; }
        }
        #pragma unroll
        for (int r = 0; r < ROWS; r++) {
            o0[rowbase + (size_t)r * K4] = tk[r];
            o2[rowbase + (size_t)r * K4] = peu[r];
        }
    }

    // ---------------- Pass B: mask LayerNorm, ONE barrier ----------------
    if (anyM) {
        const float4 w = reinterpret_cast<const float4*>(mw)[t];  // pre-barrier use
        sg[t]  = reinterpret_cast<const float4*>(gamma)[t];       // post-barrier use
        sbe[t] = reinterpret_cast<const float4*>(beta)[t];

        int m[ROWS];
        #pragma unroll
        for (int r = 0; r < ROWS; r++) m[r] = midx[b * MM + j0 + r];

        // loop1: partial sums for all rows (independent shuffle chains)
        #pragma unroll
        for (int r = 0; r < ROWS; r++) {
            const float4 pem = pe4[(size_t)m[r] * K4 + t];
            float4 x;
            x.x = pem.x + w.x; x.y = pem.y + w.y;
            x.z = pem.z + w.z; x.w = pem.w + w.w;
            float s  = x.x + x.y + x.z + x.w;
            float ss = x.x * x.x + x.y * x.y + x.z * x.z + x.w * x.w;
            #pragma unroll
            for (int o = 16; o > 0; o >>= 1) {
                s  += __shfl_xor_sync(0xffffffffu, s,  o);
                ss += __shfl_xor_sync(0xffffffffu, ss, o);
            }
            if (lane == 0) { sh_s[r][wid] = s; sh_ss[r][wid] = ss; }
        }

        __syncthreads();   // the only barrier in the block

        // loop2: finalize; pem reload hits L1 (just loaded above)
        #pragma unroll
        for (int r = 0; r < ROWS; r++) {
            float4 ln = zero;
            if (j0 + r < nmb) {
                const float sum   = sh_s[r][0]  + sh_s[r][1]  + sh_s[r][2]  + sh_s[r][3];
                const float sumsq = sh_ss[r][0] + sh_ss[r][1] + sh_ss[r][2] + sh_ss[r][3];
                const float mean  = sum * (1.0f / KK);
                const float var   = sumsq * (1.0f / KK) - mean * mean;
                const float inv   = rsqrtf(var + LN_EPS);
                const float4 pem  = pe4[(size_t)m[r] * K4 + t];   // L1 hit
                const float4 g  = sg[t];
                const float4 be = sbe[t];
                ln.x = (pem.x + w.x - mean) * inv * g.x + be.x;
                ln.y = (pem.y + w.y - mean) * inv * g.y + be.y;
                ln.z = (pem.z + w.z - mean) * inv * g.z + be.z;
                ln.w = (pem.w + w.w - mean) * inv * g.w + be.w;
            }
            o1[rowbase + (size_t)r * K4] = ln;
        }
    } else {
        #pragma unroll
        for (int r = 0; r < ROWS; r++)
            o1[rowbase + (size_t)r * K4] = zero;
    }
}

extern "C" void kernel_launch(void* const* d_in, const int* in_sizes, int n_in,
                              void* d_out, int out_size)
{
    const float* tok   = (const float*)d_in[0];
    const float* pe    = (const float*)d_in[1];
    const float* mw    = (const float*)d_in[2];
    const float* gamma = (const float*)d_in[3];
    const float* beta  = (const float*)d_in[4];
    const int*   midx  = (const int*)d_in[5];
    const int*   uidx  = (const int*)d_in[6];
    const int*   nm    = (const int*)d_in[7];
    const int*   nu    = (const int*)d_in[8];

    dim3 grid(MU / ROWS, BB);   // 256 x 32 blocks
    dim3 block(128);
    mae_masking_kernel<<<grid, block>>>(tok, pe, mw, gamma, beta,
                                        midx, uidx, nm, nu, (float*)d_out);
}

// round 10
// speedup vs baseline: 1.0276x; 1.0276x over previous
#include <cuda_runtime.h>
#include <cstdint>

// Problem constants (fixed by the dataset)
#define BB 32
#define TT 2048
#define KK 512
#define MM 1024          // MAX_MASKED
#define MU 1024          // MAX_UNMASKED
#define K4 (KK / 4)      // 128 float4 per row
#define ROWS 4           // rows per block
#define LN_EPS 1e-5f

// Round-6 structure (empirical best: 40.0us timed) restored with __stcs
// streaming stores, plus __ldcs (evict-first) on the read-once tok gather
// to keep L2 free for the heavily-reused pe table.
// Block = 128 threads, ROWS consecutive rows of one batch.
// Single __syncthreads per block; all gather loads front-batched (MLP=8).
// Outputs (concatenated in d_out):
//   out0: unmasked_embeddings (B, MU, K)
//   out1: mask_embedding      (B, MM, K)
//   out2: unmasked_positions  (B, MU, K)
__global__ __launch_bounds__(128, 8)
void mae_masking_kernel(
    const float* __restrict__ tok,    // (B, T, K)
    const float* __restrict__ pe,     // (T, K)
    const float* __restrict__ mw,     // (K, 1)
    const float* __restrict__ gamma,  // (K,)
    const float* __restrict__ beta,   // (K,)
    const int*   __restrict__ midx,   // (B, MM)
    const int*   __restrict__ uidx,   // (B, MU)
    const int*   __restrict__ nm,     // (B,)
    const int*   __restrict__ nu,     // (B,)
    float* __restrict__ out)
{
    const int j0 = blockIdx.x * ROWS;
    const int b  = blockIdx.y;
    const int t  = threadIdx.x;        // 0..127, float4 lane
    const int wid = t >> 5, lane = t & 31;

    const int nmb = nm[b];
    const int nub = nu[b];
    const bool anyM = j0 < nmb;        // block-uniform
    const bool anyU = j0 < nub;        // block-uniform

    const float4* __restrict__ pe4  = reinterpret_cast<const float4*>(pe);
    const float4* __restrict__ tok4 = reinterpret_cast<const float4*>(tok);
    float4* __restrict__ o0 = reinterpret_cast<float4*>(out);
    float4* __restrict__ o1 = o0 + (size_t)BB * MU * K4;
    float4* __restrict__ o2 = o1 + (size_t)BB * MM * K4;

    const float4 zero = make_float4(0.f, 0.f, 0.f, 0.f);
    const size_t rowbase = ((size_t)b * MU + (size_t)j0) * K4 + (size_t)t;

    __shared__ float4 sg[K4], sbe[K4];
    __shared__ float  sh_s[ROWS][4], sh_ss[ROWS][4];

    // ---------------- Pass A: pass-through copies, no syncs ----------------
    {
        float4 tk[ROWS], peu[ROWS];
        if (anyU) {
            int u[ROWS];
            #pragma unroll
            for (int r = 0; r < ROWS; r++) u[r] = uidx[b * MU + j0 + r];
            #pragma unroll
            for (int r = 0; r < ROWS; r++) {           // 8 independent loads
                if (j0 + r < nub) {
                    peu[r] = pe4[(size_t)u[r] * K4 + t];
                    tk[r]  = __ldcs(&tok4[((size_t)b * TT + (size_t)u[r]) * K4 + t]);
                } else { peu[r] = zero; tk[r] = zero; }
            }
        } else {
            #pragma unroll
            for (int r = 0; r < ROWS; r++) { peu[r] = zero; tk[r] = zero; }
        }
        #pragma unroll
        for (int r = 0; r < ROWS; r++) {
            __stcs(&o0[rowbase + (size_t)r * K4], tk[r]);
            __stcs(&o2[rowbase + (size_t)r * K4], peu[r]);
        }
    }

    // ---------------- Pass B: mask LayerNorm, ONE barrier ----------------
    if (anyM) {
        const float4 w = reinterpret_cast<const float4*>(mw)[t];  // pre-barrier use
        sg[t]  = reinterpret_cast<const float4*>(gamma)[t];       // post-barrier use
        sbe[t] = reinterpret_cast<const float4*>(beta)[t];

        int m[ROWS];
        #pragma unroll
        for (int r = 0; r < ROWS; r++) m[r] = midx[b * MM + j0 + r];

        // loop1: partial sums for all rows (independent shuffle chains)
        #pragma unroll
        for (int r = 0; r < ROWS; r++) {
            const float4 pem = pe4[(size_t)m[r] * K4 + t];
            float4 x;
            x.x = pem.x + w.x; x.y = pem.y + w.y;
            x.z = pem.z + w.z; x.w = pem.w + w.w;
            float s  = x.x + x.y + x.z + x.w;
            float ss = x.x * x.x + x.y * x.y + x.z * x.z + x.w * x.w;
            #pragma unroll
            for (int o = 16; o > 0; o >>= 1) {
                s  += __shfl_xor_sync(0xffffffffu, s,  o);
                ss += __shfl_xor_sync(0xffffffffu, ss, o);
            }
            if (lane == 0) { sh_s[r][wid] = s; sh_ss[r][wid] = ss; }
        }

        __syncthreads();   // the only barrier in the block

        // loop2: finalize; pem reload hits L1 (just loaded above)
        #pragma unroll
        for (int r = 0; r < ROWS; r++) {
            float4 ln = zero;
            if (j0 + r < nmb) {
                const float sum   = sh_s[r][0]  + sh_s[r][1]  + sh_s[r][2]  + sh_s[r][3];
                const float sumsq = sh_ss[r][0] + sh_ss[r][1] + sh_ss[r][2] + sh_ss[r][3];
                const float mean  = sum * (1.0f / KK);
                const float var   = sumsq * (1.0f / KK) - mean * mean;
                const float inv   = rsqrtf(var + LN_EPS);
                const float4 pem  = pe4[(size_t)m[r] * K4 + t];   // L1 hit
                const float4 g  = sg[t];
                const float4 be = sbe[t];
                ln.x = (pem.x + w.x - mean) * inv * g.x + be.x;
                ln.y = (pem.y + w.y - mean) * inv * g.y + be.y;
                ln.z = (pem.z + w.z - mean) * inv * g.z + be.z;
                ln.w = (pem.w + w.w - mean) * inv * g.w + be.w;
            }
            __stcs(&o1[rowbase + (size_t)r * K4], ln);
        }
    } else {
        #pragma unroll
        for (int r = 0; r < ROWS; r++)
            __stcs(&o1[rowbase + (size_t)r * K4], zero);
    }
}

extern "C" void kernel_launch(void* const* d_in, const int* in_sizes, int n_in,
                              void* d_out, int out_size)
{
    const float* tok   = (const float*)d_in[0];
    const float* pe    = (const float*)d_in[1];
    const float* mw    = (const float*)d_in[2];
    const float* gamma = (const float*)d_in[3];
    const float* beta  = (const float*)d_in[4];
    const int*   midx  = (const int*)d_in[5];
    const int*   uidx  = (const int*)d_in[6];
    const int*   nm    = (const int*)d_in[7];
    const int*   nu    = (const int*)d_in[8];

    dim3 grid(MU / ROWS, BB);   // 256 x 32 blocks
    dim3 block(128);
    mae_masking_kernel<<<grid, block>>>(tok, pe, mw, gamma, beta,
                                        midx, uidx, nm, nu, (float*)d_out);
}

// round 11
// speedup vs baseline: 1.0284x; 1.0008x over previous
#include <cuda_runtime.h>
#include <cstdint>

// Problem constants (fixed by the dataset)
#define BB 32
#define TT 2048
#define KK 512
#define MM 1024          // MAX_MASKED
#define MU 1024          // MAX_UNMASKED
#define K4 (KK / 4)      // 128 float4 per row
#define ROWS 4           // rows per block
#define LN_EPS 1e-5f

// Consolidated best: Round-6 structure (one barrier, MLP=8 front-batched
// gathers, __stcs streaming stores) + __ldcs on the read-once tok gather,
// gamma/beta loaded directly (no smem staging).
// Block = 128 threads, ROWS consecutive rows of one batch.
// Outputs (concatenated in d_out):
//   out0: unmasked_embeddings (B, MU, K)
//   out1: mask_embedding      (B, MM, K)
//   out2: unmasked_positions  (B, MU, K)
__global__ __launch_bounds__(128, 8)
void mae_masking_kernel(
    const float* __restrict__ tok,    // (B, T, K)
    const float* __restrict__ pe,     // (T, K)
    const float* __restrict__ mw,     // (K, 1)
    const float* __restrict__ gamma,  // (K,)
    const float* __restrict__ beta,   // (K,)
    const int*   __restrict__ midx,   // (B, MM)
    const int*   __restrict__ uidx,   // (B, MU)
    const int*   __restrict__ nm,     // (B,)
    const int*   __restrict__ nu,     // (B,)
    float* __restrict__ out)
{
    const int j0 = blockIdx.x * ROWS;
    const int b  = blockIdx.y;
    const int t  = threadIdx.x;        // 0..127, float4 lane
    const int wid = t >> 5, lane = t & 31;

    const int nmb = nm[b];
    const int nub = nu[b];
    const bool anyM = j0 < nmb;        // block-uniform
    const bool anyU = j0 < nub;        // block-uniform

    const float4* __restrict__ pe4  = reinterpret_cast<const float4*>(pe);
    const float4* __restrict__ tok4 = reinterpret_cast<const float4*>(tok);
    float4* __restrict__ o0 = reinterpret_cast<float4*>(out);
    float4* __restrict__ o1 = o0 + (size_t)BB * MU * K4;
    float4* __restrict__ o2 = o1 + (size_t)BB * MM * K4;

    const float4 zero = make_float4(0.f, 0.f, 0.f, 0.f);
    const size_t rowbase = ((size_t)b * MU + (size_t)j0) * K4 + (size_t)t;

    __shared__ float sh_s[ROWS][4], sh_ss[ROWS][4];

    // ---------------- Pass A: pass-through copies, no syncs ----------------
    {
        float4 tk[ROWS], peu[ROWS];
        if (anyU) {
            int u[ROWS];
            #pragma unroll
            for (int r = 0; r < ROWS; r++) u[r] = uidx[b * MU + j0 + r];
            #pragma unroll
            for (int r = 0; r < ROWS; r++) {           // 8 independent loads
                if (j0 + r < nub) {
                    peu[r] = pe4[(size_t)u[r] * K4 + t];
                    tk[r]  = __ldcs(&tok4[((size_t)b * TT + (size_t)u[r]) * K4 + t]);
                } else { peu[r] = zero; tk[r] = zero; }
            }
        } else {
            #pragma unroll
            for (int r = 0; r < ROWS; r++) { peu[r] = zero; tk[r] = zero; }
        }
        #pragma unroll
        for (int r = 0; r < ROWS; r++) {
            __stcs(&o0[rowbase + (size_t)r * K4], tk[r]);
            __stcs(&o2[rowbase + (size_t)r * K4], peu[r]);
        }
    }

    // ---------------- Pass B: mask LayerNorm, ONE barrier ----------------
    if (anyM) {
        const float4 w = reinterpret_cast<const float4*>(mw)[t];

        int m[ROWS];
        #pragma unroll
        for (int r = 0; r < ROWS; r++) m[r] = midx[b * MM + j0 + r];

        // loop1: partial sums for all rows (independent shuffle chains)
        #pragma unroll
        for (int r = 0; r < ROWS; r++) {
            const float4 pem = pe4[(size_t)m[r] * K4 + t];
            float4 x;
            x.x = pem.x + w.x; x.y = pem.y + w.y;
            x.z = pem.z + w.z; x.w = pem.w + w.w;
            float s  = x.x + x.y + x.z + x.w;
            float ss = x.x * x.x + x.y * x.y + x.z * x.z + x.w * x.w;
            #pragma unroll
            for (int o = 16; o > 0; o >>= 1) {
                s  += __shfl_xor_sync(0xffffffffu, s,  o);
                ss += __shfl_xor_sync(0xffffffffu, ss, o);
            }
            if (lane == 0) { sh_s[r][wid] = s; sh_ss[r][wid] = ss; }
        }

        __syncthreads();   // the only barrier in the block

        const float4 g  = reinterpret_cast<const float4*>(gamma)[t];  // L1/L2-hot
        const float4 be = reinterpret_cast<const float4*>(beta)[t];

        // loop2: finalize; pem reload hits L1 (just loaded above)
        #pragma unroll
        for (int r = 0; r < ROWS; r++) {
            float4 ln = zero;
            if (j0 + r < nmb) {
                const float sum   = sh_s[r][0]  + sh_s[r][1]  + sh_s[r][2]  + sh_s[r][3];
                const float sumsq = sh_ss[r][0] + sh_ss[r][1] + sh_ss[r][2] + sh_ss[r][3];
                const float mean  = sum * (1.0f / KK);
                const float var   = sumsq * (1.0f / KK) - mean * mean;
                const float inv   = rsqrtf(var + LN_EPS);
                const float4 pem  = pe4[(size_t)m[r] * K4 + t];   // L1 hit
                ln.x = (pem.x + w.x - mean) * inv * g.x + be.x;
                ln.y = (pem.y + w.y - mean) * inv * g.y + be.y;
                ln.z = (pem.z + w.z - mean) * inv * g.z + be.z;
                ln.w = (pem.w + w.w - mean) * inv * g.w + be.w;
            }
            __stcs(&o1[rowbase + (size_t)r * K4], ln);
        }
    } else {
        #pragma unroll
        for (int r = 0; r < ROWS; r++)
            __stcs(&o1[rowbase + (size_t)r * K4], zero);
    }
}

extern "C" void kernel_launch(void* const* d_in, const int* in_sizes, int n_in,
                              void* d_out, int out_size)
{
    const float* tok   = (const float*)d_in[0];
    const float* pe    = (const float*)d_in[1];
    const float* mw    = (const float*)d_in[2];
    const float* gamma = (const float*)d_in[3];
    const float* beta  = (const float*)d_in[4];
    const int*   midx  = (const int*)d_in[5];
    const int*   uidx  = (const int*)d_in[6];
    const int*   nm    = (const int*)d_in[7];
    const int*   nu    = (const int*)d_in[8];

    dim3 grid(MU / ROWS, BB);   // 256 x 32 blocks
    dim3 block(128);
    mae_masking_kernel<<<grid, block>>>(tok, pe, mw, gamma, beta,
                                        midx, uidx, nm, nu, (float*)d_out);
}

// round 12
// speedup vs baseline: 1.0894x; 1.0593x over previous
#include <cuda_runtime.h>
#include <cstdint>

// Problem constants (fixed by the dataset)
#define BB 32
#define TT 2048
#define KK 512
#define MM 1024          // MAX_MASKED
#define MU 1024          // MAX_UNMASKED
#define K4 (KK / 4)      // 128 float4 per row
#define ROWS 4           // rows per block
#define LN_EPS 1e-5f

// Round-6 configuration, byte-for-byte: the empirical timed best (40.0us).
// Block = 128 threads, ROWS consecutive rows of one batch.
// Single __syncthreads per block; all gather loads front-batched (MLP=8);
// __stcs streaming stores; default (.ca) gather loads; gamma/beta staged
// through shared memory under the single barrier.
// Outputs (concatenated in d_out):
//   out0: unmasked_embeddings (B, MU, K)
//   out1: mask_embedding      (B, MM, K)
//   out2: unmasked_positions  (B, MU, K)
__global__ __launch_bounds__(128, 8)
void mae_masking_kernel(
    const float* __restrict__ tok,    // (B, T, K)
    const float* __restrict__ pe,     // (T, K)
    const float* __restrict__ mw,     // (K, 1)
    const float* __restrict__ gamma,  // (K,)
    const float* __restrict__ beta,   // (K,)
    const int*   __restrict__ midx,   // (B, MM)
    const int*   __restrict__ uidx,   // (B, MU)
    const int*   __restrict__ nm,     // (B,)
    const int*   __restrict__ nu,     // (B,)
    float* __restrict__ out)
{
    const int j0 = blockIdx.x * ROWS;
    const int b  = blockIdx.y;
    const int t  = threadIdx.x;        // 0..127, float4 lane
    const int wid = t >> 5, lane = t & 31;

    const int nmb = nm[b];
    const int nub = nu[b];
    const bool anyM = j0 < nmb;        // block-uniform
    const bool anyU = j0 < nub;        // block-uniform

    const float4* __restrict__ pe4  = reinterpret_cast<const float4*>(pe);
    const float4* __restrict__ tok4 = reinterpret_cast<const float4*>(tok);
    float4* __restrict__ o0 = reinterpret_cast<float4*>(out);
    float4* __restrict__ o1 = o0 + (size_t)BB * MU * K4;
    float4* __restrict__ o2 = o1 + (size_t)BB * MM * K4;

    const float4 zero = make_float4(0.f, 0.f, 0.f, 0.f);
    const size_t rowbase = ((size_t)b * MU + (size_t)j0) * K4 + (size_t)t;

    __shared__ float4 sg[K4], sbe[K4];
    __shared__ float  sh_s[ROWS][4], sh_ss[ROWS][4];

    // ---------------- Pass A: pass-through copies, no syncs ----------------
    {
        float4 tk[ROWS], peu[ROWS];
        if (anyU) {
            int u[ROWS];
            #pragma unroll
            for (int r = 0; r < ROWS; r++) u[r] = uidx[b * MU + j0 + r];
            #pragma unroll
            for (int r = 0; r < ROWS; r++) {           // 8 independent loads
                if (j0 + r < nub) {
                    peu[r] = pe4[(size_t)u[r] * K4 + t];
                    tk[r]  = tok4[((size_t)b * TT + (size_t)u[r]) * K4 + t];
                } else { peu[r] = zero; tk[r] = zero; }
            }
        } else {
            #pragma unroll
            for (int r = 0; r < ROWS; r++) { peu[r] = zero; tk[r] = zero; }
        }
        #pragma unroll
        for (int r = 0; r < ROWS; r++) {
            __stcs(&o0[rowbase + (size_t)r * K4], tk[r]);
            __stcs(&o2[rowbase + (size_t)r * K4], peu[r]);
        }
    }

    // ---------------- Pass B: mask LayerNorm, ONE barrier ----------------
    if (anyM) {
        const float4 w = reinterpret_cast<const float4*>(mw)[t];  // pre-barrier use
        sg[t]  = reinterpret_cast<const float4*>(gamma)[t];       // post-barrier use
        sbe[t] = reinterpret_cast<const float4*>(beta)[t];

        int m[ROWS];
        #pragma unroll
        for (int r = 0; r < ROWS; r++) m[r] = midx[b * MM + j0 + r];

        // loop1: partial sums for all rows (independent shuffle chains)
        #pragma unroll
        for (int r = 0; r < ROWS; r++) {
            const float4 pem = pe4[(size_t)m[r] * K4 + t];
            float4 x;
            x.x = pem.x + w.x; x.y = pem.y + w.y;
            x.z = pem.z + w.z; x.w = pem.w + w.w;
            float s  = x.x + x.y + x.z + x.w;
            float ss = x.x * x.x + x.y * x.y + x.z * x.z + x.w * x.w;
            #pragma unroll
            for (int o = 16; o > 0; o >>= 1) {
                s  += __shfl_xor_sync(0xffffffffu, s,  o);
                ss += __shfl_xor_sync(0xffffffffu, ss, o);
            }
            if (lane == 0) { sh_s[r][wid] = s; sh_ss[r][wid] = ss; }
        }

        __syncthreads();   // the only barrier in the block

        // loop2: finalize; pem reload hits L1 (just loaded above)
        #pragma unroll
        for (int r = 0; r < ROWS; r++) {
            float4 ln = zero;
            if (j0 + r < nmb) {
                const float sum   = sh_s[r][0]  + sh_s[r][1]  + sh_s[r][2]  + sh_s[r][3];
                const float sumsq = sh_ss[r][0] + sh_ss[r][1] + sh_ss[r][2] + sh_ss[r][3];
                const float mean  = sum * (1.0f / KK);
                const float var   = sumsq * (1.0f / KK) - mean * mean;
                const float inv   = rsqrtf(var + LN_EPS);
                const float4 pem  = pe4[(size_t)m[r] * K4 + t];   // L1 hit
                const float4 g  = sg[t];
                const float4 be = sbe[t];
                ln.x = (pem.x + w.x - mean) * inv * g.x + be.x;
                ln.y = (pem.y + w.y - mean) * inv * g.y + be.y;
                ln.z = (pem.z + w.z - mean) * inv * g.z + be.z;
                ln.w = (pem.w + w.w - mean) * inv * g.w + be.w;
            }
            __stcs(&o1[rowbase + (size_t)r * K4], ln);
        }
    } else {
        #pragma unroll
        for (int r = 0; r < ROWS; r++)
            __stcs(&o1[rowbase + (size_t)r * K4], zero);
    }
}

extern "C" void kernel_launch(void* const* d_in, const int* in_sizes, int n_in,
                              void* d_out, int out_size)
{
    const float* tok   = (const float*)d_in[0];
    const float* pe    = (const float*)d_in[1];
    const float* mw    = (const float*)d_in[2];
    const float* gamma = (const float*)d_in[3];
    const float* beta  = (const float*)d_in[4];
    const int*   midx  = (const int*)d_in[5];
    const int*   uidx  = (const int*)d_in[6];
    const int*   nm    = (const int*)d_in[7];
    const int*   nu    = (const int*)d_in[8];

    dim3 grid(MU / ROWS, BB);   // 256 x 32 blocks
    dim3 block(128);
    mae_masking_kernel<<<grid, block>>>(tok, pe, mw, gamma, beta,
                                        midx, uidx, nm, nu, (float*)d_out);
}